// round 11
// baseline (speedup 1.0000x reference)
#include <cuda_runtime.h>

// IAF spiking layer forward; vmem matches XLA ReduceWindowRewriter's scan
// association (base_length = 16) for cumsum over T=512 — verified bitwise
// (R8/R10: rel_err == 0.0). Arithmetic identical to R8.
//
//   i = 16k + c,  k = 16s + r
//   I[i]   = sequential prefix of x within block k        (leading 0 exact)
//   SPin_k = sequential prefix of block totals within superblock s
//   C_k    = add(ET_s, SPin_k), ET_s in {0, U0}
//   vmem[i] = add(C_{k-1}, I[i])
//   s_t = ((vmem_t - sub) - 1.0 >= 0);  sub += s_t   (sub integer-exact)
//
// R11: CTA regranularization. R8's 512 CTAs / 148 SMs = 3.46 -> the 4-CTA SMs
// gate the kernel (15.6% imbalance). 128-thread blocks -> 1024 CTAs ->
// 6.92 CTAs/SM -> 1.2% imbalance. Per-thread code and fp order unchanged.

#define T_SIM 512
#define FEAT  8192

__global__ __launch_bounds__(128)
void iaf_kernel(const float* __restrict__ x, float* __restrict__ out)
{
    const int f = blockIdx.x * blockDim.x + threadIdx.x;
    const int b = blockIdx.y;

    const long long base = (long long)b * T_SIM * FEAT + f;
    const float* __restrict__ xp = x + base;
    float* __restrict__ op = out + base;

    float E    = 0.0f;   // exclusive block prefix (C_{k-1})
    float ET   = 0.0f;   // exclusive superblock prefix (0, then U0)
    float SPin = 0.0f;   // sequential fold of block totals in superblock
    float sub  = 0.0f;   // accumulated membrane subtraction (integer-exact)

    for (int k = 0; k < 32; ++k) {               // 32 blocks of 16 timesteps
        const float* __restrict__ xb = xp + (long long)k * 16 * FEAT;
        float* __restrict__ ob = op + (long long)k * 16 * FEAT;

        float I = 0.0f;                          // in-block sequential prefix
        #pragma unroll
        for (int c = 0; c < 16; ++c) {
            I = I + __ldcs(xb + c * FEAT);       // leading 0+x exact
            float v = E + I;
            float u = (v - sub) - 1.0f;
            float s = (u >= 0.0f) ? 1.0f : 0.0f;
            sub += s;
            __stcs(ob + c * FEAT, s);
        }

        // block boundary: T_k = I
        SPin = SPin + I;
        if (k == 15) {
            ET   = SPin;                         // U0 = C_15
            E    = ET;
            SPin = 0.0f;
        } else {
            E = ET + SPin;                       // C_k = add(ET, SPin)
        }
    }
}

extern "C" void kernel_launch(void* const* d_in, const int* in_sizes, int n_in,
                              void* d_out, int out_size)
{
    const float* x = (const float*)d_in[0];
    float* out = (float*)d_out;

    int total = in_sizes[0];
    int batch = total / (T_SIM * FEAT);

    dim3 block(128, 1, 1);
    dim3 grid(FEAT / 128, batch, 1);             // 64 x 16 = 1024 CTAs
    iaf_kernel<<<grid, block>>>(x, out);
}

// round 12
// speedup vs baseline: 2.9269x; 2.9269x over previous
#include <cuda_runtime.h>

// IAF spiking layer forward; vmem matches XLA ReduceWindowRewriter's scan
// association (base_length = 16) for cumsum over T=512 — verified bitwise
// (R8/R10/R11: rel_err == 0.0). Arithmetic identical to R8.
//
//   i = 16k + c,  k = 16s + r
//   I[i]   = sequential prefix of x within block k        (leading 0 exact)
//   SPin_k = sequential prefix of block totals within superblock s
//   C_k    = add(ET_s, SPin_k), ET_s in {0, U0}
//   vmem[i] = add(C_{k-1}, I[i])
//   s_t = ((vmem_t - sub) - 1.0 >= 0);  sub += s_t   (sub integer-exact)
//
// R12: FORCED MLP. R9/R11 showed ptxas silently de-pipelines this loop at
// block=128 (regs 19, 2 loads in flight, 3x slowdown). The 16 per-block loads
// are now asm volatile ld.global.cs.f32 — un-sinkable, so SASS must issue
// them back-to-back (MLP_p1=16, ~57KB/SM in flight). With codegen pinned,
// use 1024 CTAs x 128 threads: CTA-quantization loss 15.6% -> 1.2%.

#define T_SIM 512
#define FEAT  8192

__global__ __launch_bounds__(128)
void iaf_kernel(const float* __restrict__ x, float* __restrict__ out)
{
    const int f = blockIdx.x * blockDim.x + threadIdx.x;
    const int b = blockIdx.y;

    const long long base = (long long)b * T_SIM * FEAT + f;
    const float* __restrict__ xp = x + base;
    float* __restrict__ op = out + base;

    float E    = 0.0f;   // exclusive block prefix (C_{k-1})
    float ET   = 0.0f;   // exclusive superblock prefix (0, then U0)
    float SPin = 0.0f;   // sequential fold of block totals in superblock
    float sub  = 0.0f;   // accumulated membrane subtraction (integer-exact)

    for (int k = 0; k < 32; ++k) {               // 32 blocks of 16 timesteps
        const float* xb = xp + (long long)k * 16 * FEAT;
        float* ob = op + (long long)k * 16 * FEAT;

        // ---- 16 independent loads, pinned back-to-back in SASS ----
        float xv[16];
        #pragma unroll
        for (int c = 0; c < 16; ++c) {
            asm volatile("ld.global.cs.f32 %0, [%1];"
                         : "=f"(xv[c])
                         : "l"(xb + c * FEAT));
        }

        // ---- serial spike chain (identical fp order to R8) ----
        float I = 0.0f;
        #pragma unroll
        for (int c = 0; c < 16; ++c) {
            I = I + xv[c];                       // leading 0+x exact
            float v = E + I;
            float u = (v - sub) - 1.0f;
            float s = (u >= 0.0f) ? 1.0f : 0.0f;
            sub += s;
            __stcs(ob + c * FEAT, s);
        }

        // block boundary: T_k = I
        SPin = SPin + I;
        if (k == 15) {
            ET   = SPin;                         // U0 = C_15
            E    = ET;
            SPin = 0.0f;
        } else {
            E = ET + SPin;                       // C_k = add(ET, SPin)
        }
    }
}

extern "C" void kernel_launch(void* const* d_in, const int* in_sizes, int n_in,
                              void* d_out, int out_size)
{
    const float* x = (const float*)d_in[0];
    float* out = (float*)d_out;

    int total = in_sizes[0];
    int batch = total / (T_SIM * FEAT);

    dim3 block(128, 1, 1);
    dim3 grid(FEAT / 128, batch, 1);             // 64 x 16 = 1024 CTAs
    iaf_kernel<<<grid, block>>>(x, out);
}